// round 4
// baseline (speedup 1.0000x reference)
#include <cuda_runtime.h>
#include <cuda_bf16.h>

// Cascaded 16-tap FIR pair == single 33-tap causal conv for columns i >= 32:
//   y[i] = x[i] + sum_{j=1}^{32} g[j] * x[i-j],  g = [1,h] (*) [1,h_rev]
// Columns [0,32) computed exactly (v-mask aware) by threads 0-1 of block x=0.
//
// Scalar FFMA, per-thread register window loaded directly from global
// (12 front-batched LDG.128 -> MLP=12 hides DRAM latency), taps in registers.
//
// B=256 rows, N=131072 cols, F=16.

#define F       16
#define GT      33
#define THREADS 256
#define RPT     16
#define TILE    (THREADS * RPT)    // 4096
#define HALO    32
#define NCOL    131072
#define NROW    256

__global__ __launch_bounds__(THREADS, 2)
void fir2_fused(const float* __restrict__ x,
                const float* __restrict__ h,
                float* __restrict__ y)
{
    __shared__ float sg[GT];

    const int tid = threadIdx.x;
    const int row = blockIdx.y;
    const int t0  = blockIdx.x * TILE;
    const size_t rowoff = (size_t)row * NCOL;

    // ---- per-block combined taps (threads 0..32) ---------------------------
    if (tid < GT) {
        const int j = tid;
        float acc = 0.0f;
        const int a0 = (j > F) ? (j - F) : 0;
        const int a1 = (j < F) ? j : F;
        for (int a = a0; a <= a1; a++) {
            const float ka = (a == 0) ? 1.0f : __ldg(h + a - 1);
            const int bb = j - a;
            const float kb = (bb == 0) ? 1.0f : __ldg(h + F - bb);
            acc += ka * kb;
        }
        sg[j] = acc;
    }
    __syncthreads();

    const bool edge = (blockIdx.x == 0) && (tid < 2);

    if (!edge) {
        // ---- front-batched window load: w[c] = x[row][base + c], c in [0,48)
        const int base = t0 + tid * RPT - HALO;   // 64B-aligned, >= 0 here
        const float4* xp = reinterpret_cast<const float4*>(x + rowoff + base);

        float w[RPT + HALO];                      // 48 floats, 12 LDG.128
#pragma unroll
        for (int q = 0; q < (RPT + HALO) / 4; q++)
            *reinterpret_cast<float4*>(&w[4 * q]) = xp[q];

        // Taps -> registers (uniform broadcast LDS; hoisted once).
        float g[GT];
#pragma unroll
        for (int j = 0; j < GT; j++) g[j] = sg[j];

        // ---- 16 outputs, 32 FFMA each; result overwrites consumed slot -----
#pragma unroll
        for (int r = 0; r < RPT; r++) {
            float acc = w[r + HALO];              // identity tap g[0] = 1
#pragma unroll
            for (int j = 1; j < GT; j++)
                acc = fmaf(g[j], w[r + HALO - j], acc);
            w[r] = acc;   // out[r] -> w[r]; later outputs only read w[>r]
        }

        float4* yo = reinterpret_cast<float4*>(y + rowoff + t0 + tid * RPT);
#pragma unroll
        for (int q = 0; q < RPT / 4; q++)
            yo[q] = make_float4(w[4 * q], w[4 * q + 1],
                                w[4 * q + 2], w[4 * q + 3]);
    } else {
        // ---- exact masked two-stage result for columns [0,32) --------------
        if (tid == 0) {
            float4* yo = reinterpret_cast<float4*>(y + rowoff);
#pragma unroll
            for (int q = 0; q < 4; q++)
                yo[q] = make_float4(0.f, 0.f, 0.f, 0.f);   // y[0..15] = 0
        } else {
            const float* xr = x + rowoff;
            float xa[32];
#pragma unroll
            for (int c = 0; c < 32; c++) xa[c] = xr[c];
            float hh[F];
#pragma unroll
            for (int j = 0; j < F; j++) hh[j] = __ldg(h + j);

            float va[F];           // v[16..31]
#pragma unroll
            for (int t = 0; t < F; t++) {
                const int k = F + t;
                float acc = xa[k];
#pragma unroll
                for (int j = 0; j < F; j++)
                    acc = fmaf(hh[j], xa[k - 1 - j], acc);
                va[t] = acc;
            }
            float ya[F];           // y[16..31]
#pragma unroll
            for (int t = 0; t < F; t++) {
                const int i = F + t;
                float acc = va[t];
#pragma unroll
                for (int m = 0; m < F; m++) {
                    const int k = i - F + m;      // v index; masked if < 16
                    if (k >= F) acc = fmaf(hh[m], va[k - F], acc);
                }
                ya[t] = acc;
            }
            float4* yo = reinterpret_cast<float4*>(y + rowoff + F);
#pragma unroll
            for (int q = 0; q < 4; q++)
                yo[q] = make_float4(ya[4 * q], ya[4 * q + 1],
                                    ya[4 * q + 2], ya[4 * q + 3]);
        }
    }
}

extern "C" void kernel_launch(void* const* d_in, const int* in_sizes, int n_in,
                              void* d_out, int out_size)
{
    const float* x = (const float*)d_in[0];   // (256, 131072) f32
    const float* h = (const float*)d_in[1];   // (1, 16) f32
    float* y = (float*)d_out;                 // (256, 131072) f32

    dim3 grid(NCOL / TILE, NROW);
    fir2_fused<<<grid, THREADS>>>(x, h, y);
}

// round 5
// speedup vs baseline: 1.4524x; 1.4524x over previous
#include <cuda_runtime.h>
#include <cuda_bf16.h>

// Cascaded 16-tap FIR pair == single 33-tap causal conv for columns i >= 32:
//   y[i] = x[i] + sum_{j=1}^{32} g[j] * x[i-j],  g = [1,h] (*) [1,h_rev]
// Columns [0,32) computed exactly (v-mask aware) by threads 0-1 of block x=0.
//
// smem tile with 16->20 segment padding (conflict-free 80B-stride LDS.128),
// chunked taps (4 x 8 from smem) to keep regs <= ~82 -> 3 CTAs/SM.
//
// B=256 rows, N=131072 cols, F=16.

#define F       16
#define GT      33
#define THREADS 256
#define RPT     16
#define TILE    (THREADS * RPT)    // 4096
#define HALO    32
#define NCOL    131072
#define NROW    256

#define NSEG    ((TILE + HALO) / 16)      // 258 segments of 16 floats
#define SEGP    20                         // padded segment stride (floats)

__global__ __launch_bounds__(THREADS, 3)
void fir2_fused(const float* __restrict__ x,
                const float* __restrict__ h,
                float* __restrict__ y)
{
    __shared__ float sg[GT + 3];
    __shared__ float sx[NSEG * SEGP];      // padded tile: seg s at sx[20*s]

    const int tid = threadIdx.x;
    const int row = blockIdx.y;
    const int t0  = blockIdx.x * TILE;
    const size_t rowoff = (size_t)row * NCOL;

    // ---- per-block combined taps (threads 0..32) ---------------------------
    if (tid < GT) {
        const int j = tid;
        float acc = 0.0f;
        const int a0 = (j > F) ? (j - F) : 0;
        const int a1 = (j < F) ? j : F;
        for (int a = a0; a <= a1; a++) {
            const float ka = (a == 0) ? 1.0f : __ldg(h + a - 1);
            const int bb = j - a;
            const float kb = (bb == 0) ? 1.0f : __ldg(h + F - bb);
            acc += ka * kb;
        }
        sg[j] = acc;
    }

    // ---- coalesced staging into padded smem --------------------------------
    // logical float k (k in [0, TILE+HALO)) = x[row][t0 - 32 + k]
    // padded float4 slot for vec vk: seg = vk/4, lane = vk%4 -> f4 index seg*5+lane
    {
        const float4* src = reinterpret_cast<const float4*>(x + rowoff + t0 - HALO);
        float4* dst = reinterpret_cast<float4*>(sx);
        const int nvec = (TILE + HALO) / 4;          // 1032
        if (blockIdx.x == 0) {
            for (int vk = tid; vk < nvec; vk += THREADS) {
                float4 v = (vk >= HALO / 4) ? src[vk] : make_float4(0.f, 0.f, 0.f, 0.f);
                dst[(vk >> 2) * 5 + (vk & 3)] = v;
            }
        } else {
#pragma unroll
            for (int vk = tid; vk < nvec; vk += THREADS) {
                float4 v = src[vk];
                dst[(vk >> 2) * 5 + (vk & 3)] = v;
            }
        }
    }
    __syncthreads();

    const bool edge = (blockIdx.x == 0) && (tid < 2);

    if (!edge) {
        // ---- window: w[c] = x[row][t0 + tid*16 - 32 + c], c in [0,48) ------
        // = logical floats [16*(tid-2+2) ... ) -> segments tid, tid+1, tid+2
        // wait: logical k = tid*16 - 32 + c + 32 = tid*16 + c  (since staging
        // base is t0-32). So segments tid, tid+1, tid+2.
        float w[RPT + HALO];
        {
            const float4* sp = reinterpret_cast<const float4*>(sx);
#pragma unroll
            for (int s = 0; s < 3; s++) {
                const int fb = (tid + s) * 5;        // float4 base of segment
#pragma unroll
                for (int q = 0; q < 4; q++)
                    *reinterpret_cast<float4*>(&w[16 * s + 4 * q]) = sp[fb + q];
            }
        }

        // ---- accumulate: identity tap then 4 chunks of 8 taps --------------
        float acc[RPT];
#pragma unroll
        for (int r = 0; r < RPT; r++) acc[r] = w[r + HALO];

#pragma unroll
        for (int c = 0; c < 4; c++) {
            float t[8];
#pragma unroll
            for (int k = 0; k < 8; k++) t[k] = sg[8 * c + 1 + k];
#pragma unroll
            for (int r = 0; r < RPT; r++) {
#pragma unroll
                for (int k = 0; k < 8; k++)
                    acc[r] = fmaf(t[k], w[r + 31 - 8 * c - k], acc[r]);
            }
        }

        float4* yo = reinterpret_cast<float4*>(y + rowoff + t0 + tid * RPT);
#pragma unroll
        for (int q = 0; q < RPT / 4; q++)
            yo[q] = make_float4(acc[4 * q], acc[4 * q + 1],
                                acc[4 * q + 2], acc[4 * q + 3]);
    } else {
        // ---- exact masked two-stage result for columns [0,32) --------------
        if (tid == 0) {
            float4* yo = reinterpret_cast<float4*>(y + rowoff);
#pragma unroll
            for (int q = 0; q < 4; q++)
                yo[q] = make_float4(0.f, 0.f, 0.f, 0.f);   // y[0..15] = 0
        } else {
            const float* xr = x + rowoff;
            float xa[32];
#pragma unroll
            for (int c = 0; c < 32; c++) xa[c] = xr[c];
            float hh[F];
#pragma unroll
            for (int j = 0; j < F; j++) hh[j] = __ldg(h + j);

            float va[F];           // v[16..31]
#pragma unroll
            for (int t = 0; t < F; t++) {
                const int k = F + t;
                float a2 = xa[k];
#pragma unroll
                for (int j = 0; j < F; j++)
                    a2 = fmaf(hh[j], xa[k - 1 - j], a2);
                va[t] = a2;
            }
            float ya[F];           // y[16..31]
#pragma unroll
            for (int t = 0; t < F; t++) {
                const int i = F + t;
                float a2 = va[t];
#pragma unroll
                for (int m = 0; m < F; m++) {
                    const int k = i - F + m;      // v index; masked if < 16
                    if (k >= F) a2 = fmaf(hh[m], va[k - F], a2);
                }
                ya[t] = a2;
            }
            float4* yo = reinterpret_cast<float4*>(y + rowoff + F);
#pragma unroll
            for (int q = 0; q < 4; q++)
                yo[q] = make_float4(ya[4 * q], ya[4 * q + 1],
                                    ya[4 * q + 2], ya[4 * q + 3]);
        }
    }
}

extern "C" void kernel_launch(void* const* d_in, const int* in_sizes, int n_in,
                              void* d_out, int out_size)
{
    const float* x = (const float*)d_in[0];   // (256, 131072) f32
    const float* h = (const float*)d_in[1];   // (1, 16) f32
    float* y = (float*)d_out;                 // (256, 131072) f32

    dim3 grid(NCOL / TILE, NROW);
    fir2_fused<<<grid, THREADS>>>(x, h, y);
}